// round 14
// baseline (speedup 1.0000x reference)
#include <cuda_runtime.h>
#include <cuda_fp16.h>
#include <cstdint>

#define BB 32768
#define IN 512
#define HID 256
#define OUT 128
#define NE 16
#define CTX 256
#define DEMO 16
#define GATE_IN 784

// ---------------- device scratch: fp16 pairs packed in u32 along K ----------------
__device__ uint32_t g_xh[BB * IN / 2];           // x  as fp16x2
__device__ uint32_t g_w1h[NE * HID * IN / 2];    // W1 as fp16x2
__device__ uint32_t g_w2h[NE * OUT * HID / 2];   // W2 as fp16x2
__device__ float    g_wgt[BB * NE];              // softmax gate weights

// ---------------- helpers ----------------
__device__ __forceinline__ uint32_t pack_h2(float a, float b) {
    __half2 h = __floats2half2_rn(a, b);
    return *(uint32_t*)&h;
}
__device__ __forceinline__ void cp16(void* s, const void* g) {
    uint32_t sa = (uint32_t)__cvta_generic_to_shared(s);
    asm volatile("cp.async.cg.shared.global [%0], [%1], 16;" :: "r"(sa), "l"(g));
}
__device__ __forceinline__ void cp_commit() { asm volatile("cp.async.commit_group;"); }
__device__ __forceinline__ void cp_wait0()  { asm volatile("cp.async.wait_group 0;" ::: "memory"); }
__device__ __forceinline__ void cp_wait1()  { asm volatile("cp.async.wait_group 1;" ::: "memory"); }

__device__ __forceinline__ void mma_f16(float* c, const uint32_t* a,
                                        uint32_t b0, uint32_t b1) {
    asm volatile(
        "mma.sync.aligned.m16n8k16.row.col.f32.f16.f16.f32 "
        "{%0,%1,%2,%3},{%4,%5,%6,%7},{%8,%9},{%0,%1,%2,%3};\n"
        : "+f"(c[0]), "+f"(c[1]), "+f"(c[2]), "+f"(c[3])
        : "r"(a[0]), "r"(a[1]), "r"(a[2]), "r"(a[3]), "r"(b0), "r"(b1));
}

// ---------------- gate2: tensor-core gate + fused conversions (R13 proven) ----------------
#define W1_F4 (NE * HID * IN / 4)
#define W2_F4 (NE * OUT * HID / 4)
#define GWS_STRIDE 396
#define GBUF_OFF  6336
#define GBUF_SZ   4608
#define GATE2_SMEM ((GBUF_OFF + 2 * GBUF_SZ) * 4)   // 62208 B

__global__ __launch_bounds__(256) void gate2_k(
    const float* __restrict__ u, const float* __restrict__ x,
    const float* __restrict__ d, const float* __restrict__ gW,
    const float* __restrict__ gb,
    const float* __restrict__ W1, const float* __restrict__ W2) {
    extern __shared__ uint32_t gsm[];
    const int tid = threadIdx.x;
    const int b0 = blockIdx.x * 128;

    {
        int gtid = blockIdx.x * 256 + tid;
        const int nthr = 256 * 256;
        for (int i = gtid; i < W1_F4; i += nthr) {
            float4 v = ((const float4*)W1)[i];
            g_w1h[2 * i]     = pack_h2(v.x, v.y);
            g_w1h[2 * i + 1] = pack_h2(v.z, v.w);
        }
        for (int i = gtid; i < W2_F4; i += nthr) {
            float4 v = ((const float4*)W2)[i];
            g_w2h[2 * i]     = pack_h2(v.x, v.y);
            g_w2h[2 * i + 1] = pack_h2(v.z, v.w);
        }
    }

    for (int i = tid; i < NE * (GATE_IN / 2); i += 256) {
        int e = i / 392, kp = i - e * 392;
        const float* s = gW + e * GATE_IN + 2 * kp;
        gsm[e * GWS_STRIDE + kp] = pack_h2(s[0], s[1]);
    }
    __syncthreads();

    const int warp = tid >> 5, lane = tid & 31;
    const int g = lane >> 2, t = lane & 3;
    float acc[2][4];
    #pragma unroll
    for (int nf = 0; nf < 2; ++nf)
        #pragma unroll
        for (int c = 0; c < 4; ++c) acc[nf][c] = 0.f;

    for (int c = 0; c < 13; ++c) {
        uint32_t* buf = gsm + GBUF_OFF + (c & 1) * GBUF_SZ;
        if (c < 4) {
            const float* src = u + (size_t)b0 * CTX + c * 64;
            #pragma unroll
            for (int j = 0; j < 16; ++j) {
                int v = tid + j * 256; int r = v >> 5, q = v & 31;
                const float* s = src + (size_t)r * CTX + 2 * q;
                buf[r * 36 + q] = pack_h2(s[0], s[1]);
            }
        } else if (c < 12) {
            const float* src = x + (size_t)b0 * IN + (c - 4) * 64;
            #pragma unroll
            for (int j = 0; j < 16; ++j) {
                int v = tid + j * 256; int r = v >> 5, q = v & 31;
                const float* s = src + (size_t)r * IN + 2 * q;
                uint32_t ph = pack_h2(s[0], s[1]);
                buf[r * 36 + q] = ph;
                g_xh[(size_t)(b0 + r) * (IN / 2) + (c - 4) * 32 + q] = ph;
            }
        } else {
            const float* src = d + (size_t)b0 * DEMO;
            #pragma unroll
            for (int j = 0; j < 4; ++j) {
                int v = tid + j * 256; int r = v >> 3, q = v & 7;
                const float* s = src + (size_t)r * DEMO + 2 * q;
                buf[r * 36 + q] = pack_h2(s[0], s[1]);
            }
        }
        __syncthreads();

        const int nks = (c == 12) ? 1 : 4;
        const int r = warp * 16 + g;
        for (int ks = 0; ks < nks; ++ks) {
            const int pb = ks * 8;
            uint32_t a[4];
            a[0] = buf[r * 36 + pb + t];
            a[1] = buf[(r + 8) * 36 + pb + t];
            a[2] = buf[r * 36 + pb + t + 4];
            a[3] = buf[(r + 8) * 36 + pb + t + 4];
            const int kp = c * 32 + pb;
            #pragma unroll
            for (int nf = 0; nf < 2; ++nf) {
                int n = nf * 8 + g;
                uint32_t bb0 = gsm[n * GWS_STRIDE + kp + t];
                uint32_t bb1 = gsm[n * GWS_STRIDE + kp + t + 4];
                mma_f16(acc[nf], a, bb0, bb1);
            }
        }
        __syncthreads();
    }

    float gb00 = gb[2 * t],     gb01 = gb[2 * t + 1];
    float gb10 = gb[8 + 2 * t], gb11 = gb[9 + 2 * t];
    const int rbase = b0 + warp * 16;
    #pragma unroll
    for (int half = 0; half < 2; ++half) {
        float v0 = acc[0][half * 2 + 0] + gb00;
        float v1 = acc[0][half * 2 + 1] + gb01;
        float v2 = acc[1][half * 2 + 0] + gb10;
        float v3 = acc[1][half * 2 + 1] + gb11;
        float m = fmaxf(fmaxf(v0, v1), fmaxf(v2, v3));
        m = fmaxf(m, __shfl_xor_sync(0xffffffffu, m, 1));
        m = fmaxf(m, __shfl_xor_sync(0xffffffffu, m, 2));
        float p0 = expf(v0 - m), p1 = expf(v1 - m);
        float p2 = expf(v2 - m), p3 = expf(v3 - m);
        float s = p0 + p1 + p2 + p3;
        s += __shfl_xor_sync(0xffffffffu, s, 1);
        s += __shfl_xor_sync(0xffffffffu, s, 2);
        float inv = 1.f / s;
        int row = rbase + g + half * 8;
        g_wgt[(size_t)row * NE + 2 * t]     = p0 * inv;
        g_wgt[(size_t)row * NE + 2 * t + 1] = p1 * inv;
        g_wgt[(size_t)row * NE + 8 + 2 * t] = p2 * inv;
        g_wgt[(size_t)row * NE + 9 + 2 * t] = p3 * inv;
    }
}

// ---------------- moe_main: M=64 tile, K=32 chunks, 2 CTAs/SM ----------------
// SMEM u32 layout (25344 u32 = 101376 B):
//   [0, 3840)       XA: 3 x (64*20)
//   [3840, 19200)   WA: 3 x (256*20)
//     Hs (64 x 132 = 8448) aliases [0, 8448)  (live: epilogue A -> end of phase B)
//   [19200, 24320)  W2: 2 x (128*20)
//   [24320, 25344)  wts (float) 64 x 16
#define XA_OFF  0
#define XA_BUF  1280
#define WA_OFF  3840
#define WA_BUF  5120
#define HS_STRIDE 132
#define W2_OFF  19200
#define W2_BUF  2560
#define WTS_OFF 24320
#define SMEM_BYTES (25344 * 4)

// K=32 chunk: 16 u32 (fp16-pairs) per row, row stride 20
__device__ __forceinline__ void stageA(uint32_t* sm, int tid, int b0, int e, int ci, int buf) {
    uint32_t* xs = sm + XA_OFF + buf * XA_BUF;
    uint32_t* ws = sm + WA_OFF + buf * WA_BUF;
    const uint32_t* xsrc = g_xh + (size_t)b0 * (IN / 2) + ci * 16;
    const uint32_t* wsrc = g_w1h + (size_t)e * HID * (IN / 2) + ci * 16;
    {                                           // X: 64 rows x 16 u32 (256 cp16)
        int r = tid >> 2, q = (tid & 3) * 4;
        cp16(xs + r * 20 + q, xsrc + (size_t)r * (IN / 2) + q);
    }
    #pragma unroll
    for (int j = 0; j < 4; ++j) {               // W1: 256 rows x 16 u32 (1024 cp16)
        int v = tid + j * 256;
        int n = v >> 2, q = (v & 3) * 4;
        cp16(ws + n * 20 + q, wsrc + (size_t)n * (IN / 2) + q);
    }
}
__device__ __forceinline__ void stageB(uint32_t* sm, int tid, int e, int ci, int buf) {
    uint32_t* w2 = sm + W2_OFF + buf * W2_BUF;
    const uint32_t* src = g_w2h + (size_t)e * OUT * (HID / 2) + ci * 16;
    #pragma unroll
    for (int j = 0; j < 2; ++j) {               // W2: 128 rows x 16 u32 (512 cp16)
        int v = tid + j * 256;
        int o = v >> 2, q = (v & 3) * 4;
        cp16(w2 + o * 20 + q, src + (size_t)o * (HID / 2) + q);
    }
}

__global__ __launch_bounds__(256, 2) void moe_main(
    const float* __restrict__ b1, const float* __restrict__ b2,
    float* __restrict__ out) {
    extern __shared__ uint32_t smu[];
    const int tid  = threadIdx.x;
    const int warp = tid >> 5, lane = tid & 31;
    const int g = lane >> 2, t = lane & 3;
    const int b0 = blockIdx.x * 64;

    float* wts = (float*)(smu + WTS_OFF);
    for (int i = tid; i < 64 * NE; i += 256) wts[i] = g_wgt[(size_t)b0 * NE + i];

    // warp tiling: 2 (M) x 4 (N) warps; warp tile 32 x 64 (A) / 32 x 32 (B)
    const int wm  = (warp & 1) * 32;   // row base (both phases)
    const int wn1 = (warp >> 1) * 64;  // phase-A col base (HID=256)
    const int wn2 = (warp >> 1) * 32;  // phase-B col base (OUT=128)

    float acc2[2][4][4];               // persistent mixture accumulator
    #pragma unroll
    for (int a = 0; a < 2; ++a)
        #pragma unroll
        for (int b = 0; b < 4; ++b)
            #pragma unroll
            for (int c = 0; c < 4; ++c) acc2[a][b][c] = 0.f;

    __syncthreads();

    for (int e = 0; e < NE; ++e) {
        // ===== Phase A: H = relu(X @ W1_e^T + b1) * w  (K=512, 16 chunks of 32) =====
        float acc1[2][8][4];
        #pragma unroll
        for (int a = 0; a < 2; ++a)
            #pragma unroll
            for (int b = 0; b < 8; ++b)
                #pragma unroll
                for (int c = 0; c < 4; ++c) acc1[a][b][c] = 0.f;

        stageA(smu, tid, b0, e, 0, 0); cp_commit();
        stageA(smu, tid, b0, e, 1, 1); cp_commit();

        for (int ci = 0; ci < 16; ++ci) {
            if (ci < 15) cp_wait1(); else cp_wait0();  // oldest group complete
            __syncthreads();                           // data visible + buffer(ci+2) free
            if (ci < 14) { stageA(smu, tid, b0, e, ci + 2, (ci + 2) % 3); cp_commit(); }
            const uint32_t* xp = smu + XA_OFF + (ci % 3) * XA_BUF;
            const uint32_t* wp = smu + WA_OFF + (ci % 3) * WA_BUF;
            #pragma unroll
            for (int ks = 0; ks < 2; ++ks) {           // two k16 slices per K=32 chunk
                const int pb = ks * 8;
                uint32_t a[2][4];
                #pragma unroll
                for (int mf = 0; mf < 2; ++mf) {
                    int r = wm + mf * 16 + g;
                    a[mf][0] = xp[r * 20 + pb + t];
                    a[mf][1] = xp[(r + 8) * 20 + pb + t];
                    a[mf][2] = xp[r * 20 + pb + t + 4];
                    a[mf][3] = xp[(r + 8) * 20 + pb + t + 4];
                }
                #pragma unroll
                for (int nf = 0; nf < 8; ++nf) {
                    int n = wn1 + nf * 8 + g;
                    uint32_t bb0 = wp[n * 20 + pb + t];
                    uint32_t bb1 = wp[n * 20 + pb + t + 4];
                    #pragma unroll
                    for (int mf = 0; mf < 2; ++mf)
                        mma_f16(acc1[mf][nf], a[mf], bb0, bb1);
                }
            }
        }

        // prefetch W2 chunk0 (separate region; lands during epilogue)
        stageB(smu, tid, e, 0, 0); cp_commit();
        __syncthreads();   // all warps done reading A buffers before Hs (aliased) is written

        // epilogue A: relu + bias + gate-weight scale, fp16 pack, store H
        #pragma unroll
        for (int mf = 0; mf < 2; ++mf) {
            int r0 = wm + mf * 16 + g, r1 = r0 + 8;
            float w0 = wts[r0 * NE + e], w1 = wts[r1 * NE + e];
            #pragma unroll
            for (int nf = 0; nf < 8; ++nf) {
                int c0 = wn1 + nf * 8 + 2 * t;
                int p  = c0 >> 1;
                float bb0 = b1[e * HID + c0], bb1 = b1[e * HID + c0 + 1];
                float v00 = fmaxf(acc1[mf][nf][0] + bb0, 0.f) * w0;
                float v01 = fmaxf(acc1[mf][nf][1] + bb1, 0.f) * w0;
                float v10 = fmaxf(acc1[mf][nf][2] + bb0, 0.f) * w1;
                float v11 = fmaxf(acc1[mf][nf][3] + bb1, 0.f) * w1;
                smu[r0 * HS_STRIDE + p] = pack_h2(v00, v01);
                smu[r1 * HS_STRIDE + p] = pack_h2(v10, v11);
            }
        }

        // ===== Phase B: out += (w*H_e) @ W2_e^T  (K=256, 8 chunks of 32) =====
        for (int ci = 0; ci < 8; ++ci) {
            int cur = ci & 1;
            cp_wait0(); __syncthreads();   // W2[cur] ready; ci==0 also publishes Hs stores
            if (ci < 7) { stageB(smu, tid, e, ci + 1, cur ^ 1); cp_commit(); }
            const uint32_t* w2p = smu + W2_OFF + cur * W2_BUF;
            #pragma unroll
            for (int ks = 0; ks < 2; ++ks) {
                const int pb  = ci * 16 + ks * 8;     // pair base into Hs
                const int pb2 = ks * 8;               // within W2 tile
                uint32_t a[2][4];
                #pragma unroll
                for (int mf = 0; mf < 2; ++mf) {
                    int r = wm + mf * 16 + g;
                    a[mf][0] = smu[r * HS_STRIDE + pb + t];
                    a[mf][1] = smu[(r + 8) * HS_STRIDE + pb + t];
                    a[mf][2] = smu[r * HS_STRIDE + pb + t + 4];
                    a[mf][3] = smu[(r + 8) * HS_STRIDE + pb + t + 4];
                }
                #pragma unroll
                for (int nf = 0; nf < 4; ++nf) {
                    int n = wn2 + nf * 8 + g;
                    uint32_t bb0 = w2p[n * 20 + pb2 + t];
                    uint32_t bb1 = w2p[n * 20 + pb2 + t + 4];
                    #pragma unroll
                    for (int mf = 0; mf < 2; ++mf)
                        mma_f16(acc2[mf][nf], a[mf], bb0, bb1);
                }
            }
            __syncthreads();   // all warps done with buf cur (and Hs at ci==7) before reuse
        }
    }

    // ===== epilogue: out = acc2 + sum_e w[b,e] * b2[e,:] =====
    #pragma unroll
    for (int mf = 0; mf < 2; ++mf) {
        int r0 = wm + mf * 16 + g, r1 = r0 + 8;
        #pragma unroll
        for (int nf = 0; nf < 4; ++nf) {
            int c0 = wn2 + nf * 8 + 2 * t;
            float s0 = acc2[mf][nf][0], s1 = acc2[mf][nf][1];
            float s2 = acc2[mf][nf][2], s3 = acc2[mf][nf][3];
            #pragma unroll
            for (int e = 0; e < NE; ++e) {
                float bb0 = b2[e * OUT + c0], bb1 = b2[e * OUT + c0 + 1];
                float we0 = wts[r0 * NE + e], we1 = wts[r1 * NE + e];
                s0 += we0 * bb0; s1 += we0 * bb1;
                s2 += we1 * bb0; s3 += we1 * bb1;
            }
            out[(size_t)(b0 + r0) * OUT + c0]     = s0;
            out[(size_t)(b0 + r0) * OUT + c0 + 1] = s1;
            out[(size_t)(b0 + r1) * OUT + c0]     = s2;
            out[(size_t)(b0 + r1) * OUT + c0 + 1] = s3;
        }
    }
}

// ---------------- launch (2 kernels) ----------------
extern "C" void kernel_launch(void* const* d_in, const int* in_sizes, int n_in,
                              void* d_out, int out_size) {
    const float* x  = (const float*)d_in[0];
    const float* u  = (const float*)d_in[1];
    const float* dd = (const float*)d_in[2];
    const float* gW = (const float*)d_in[3];
    const float* gb = (const float*)d_in[4];
    const float* W1 = (const float*)d_in[5];
    const float* b1 = (const float*)d_in[6];
    const float* W2 = (const float*)d_in[7];
    const float* b2 = (const float*)d_in[8];
    float* out = (float*)d_out;

    cudaFuncSetAttribute(gate2_k, cudaFuncAttributeMaxDynamicSharedMemorySize,
                         GATE2_SMEM);
    cudaFuncSetAttribute(moe_main, cudaFuncAttributeMaxDynamicSharedMemorySize,
                         SMEM_BYTES);

    gate2_k<<<BB / 128, 256, GATE2_SMEM>>>(u, x, dd, gW, gb, W1, W2);
    moe_main<<<BB / 64, 256, SMEM_BYTES>>>(b1, b2, out);
}

// round 16
// speedup vs baseline: 1.9134x; 1.9134x over previous
#include <cuda_runtime.h>
#include <cuda_fp16.h>
#include <cstdint>

#define BB 32768
#define IN 512
#define HID 256
#define OUT 128
#define NE 16
#define CTX 256
#define DEMO 16
#define GATE_IN 784

// ---------------- device scratch: fp16 pairs packed in u32 along K ----------------
__device__ uint32_t g_xh[BB * IN / 2];           // x  as fp16x2
__device__ uint32_t g_w1h[NE * HID * IN / 2];    // W1 as fp16x2
__device__ uint32_t g_w2h[NE * OUT * HID / 2];   // W2 as fp16x2
__device__ float    g_wgt[BB * NE];              // softmax gate weights

// ---------------- helpers ----------------
__device__ __forceinline__ uint32_t pack_h2(float a, float b) {
    __half2 h = __floats2half2_rn(a, b);
    return *(uint32_t*)&h;
}
__device__ __forceinline__ uint32_t smem_u32p(const void* p) {
    uint32_t a;
    asm("{ .reg .u64 t; cvta.to.shared.u64 t, %1; cvt.u32.u64 %0, t; }" : "=r"(a) : "l"(p));
    return a;
}
__device__ __forceinline__ void cp16(void* s, const void* g) {
    uint32_t sa = (uint32_t)__cvta_generic_to_shared(s);
    asm volatile("cp.async.cg.shared.global [%0], [%1], 16;" :: "r"(sa), "l"(g));
}
__device__ __forceinline__ void cp_commit() { asm volatile("cp.async.commit_group;"); }
__device__ __forceinline__ void cp_wait0()  { asm volatile("cp.async.wait_group 0;" ::: "memory"); }
__device__ __forceinline__ void cp_wait1()  { asm volatile("cp.async.wait_group 1;" ::: "memory"); }

__device__ __forceinline__ void mma_f16(float* c, const uint32_t* a,
                                        uint32_t b0, uint32_t b1) {
    asm volatile(
        "mma.sync.aligned.m16n8k16.row.col.f32.f16.f16.f32 "
        "{%0,%1,%2,%3},{%4,%5,%6,%7},{%8,%9},{%0,%1,%2,%3};\n"
        : "+f"(c[0]), "+f"(c[1]), "+f"(c[2]), "+f"(c[3])
        : "r"(a[0]), "r"(a[1]), "r"(a[2]), "r"(a[3]), "r"(b0), "r"(b1));
}
__device__ __forceinline__ void ldsm_x4(uint32_t* r, uint32_t addr) {
    asm volatile("ldmatrix.sync.aligned.m8n8.x4.shared.b16 {%0,%1,%2,%3}, [%4];"
        : "=r"(r[0]), "=r"(r[1]), "=r"(r[2]), "=r"(r[3]) : "r"(addr));
}

// ---------------- gate2: tensor-core gate + fused conversions (R13 proven) ----------------
#define W1_F4 (NE * HID * IN / 4)
#define W2_F4 (NE * OUT * HID / 4)
#define GWS_STRIDE 396
#define GBUF_OFF  6336
#define GBUF_SZ   4608
#define GATE2_SMEM ((GBUF_OFF + 2 * GBUF_SZ) * 4)   // 62208 B

__global__ __launch_bounds__(256) void gate2_k(
    const float* __restrict__ u, const float* __restrict__ x,
    const float* __restrict__ d, const float* __restrict__ gW,
    const float* __restrict__ gb,
    const float* __restrict__ W1, const float* __restrict__ W2) {
    extern __shared__ uint32_t gsm[];
    const int tid = threadIdx.x;
    const int b0 = blockIdx.x * 128;

    {
        int gtid = blockIdx.x * 256 + tid;
        const int nthr = 256 * 256;
        for (int i = gtid; i < W1_F4; i += nthr) {
            float4 v = ((const float4*)W1)[i];
            g_w1h[2 * i]     = pack_h2(v.x, v.y);
            g_w1h[2 * i + 1] = pack_h2(v.z, v.w);
        }
        for (int i = gtid; i < W2_F4; i += nthr) {
            float4 v = ((const float4*)W2)[i];
            g_w2h[2 * i]     = pack_h2(v.x, v.y);
            g_w2h[2 * i + 1] = pack_h2(v.z, v.w);
        }
    }

    for (int i = tid; i < NE * (GATE_IN / 2); i += 256) {
        int e = i / 392, kp = i - e * 392;
        const float* s = gW + e * GATE_IN + 2 * kp;
        gsm[e * GWS_STRIDE + kp] = pack_h2(s[0], s[1]);
    }
    __syncthreads();

    const int warp = tid >> 5, lane = tid & 31;
    const int g = lane >> 2, t = lane & 3;
    float acc[2][4];
    #pragma unroll
    for (int nf = 0; nf < 2; ++nf)
        #pragma unroll
        for (int c = 0; c < 4; ++c) acc[nf][c] = 0.f;

    for (int c = 0; c < 13; ++c) {
        uint32_t* buf = gsm + GBUF_OFF + (c & 1) * GBUF_SZ;
        if (c < 4) {
            const float* src = u + (size_t)b0 * CTX + c * 64;
            #pragma unroll
            for (int j = 0; j < 16; ++j) {
                int v = tid + j * 256; int r = v >> 5, q = v & 31;
                const float* s = src + (size_t)r * CTX + 2 * q;
                buf[r * 36 + q] = pack_h2(s[0], s[1]);
            }
        } else if (c < 12) {
            const float* src = x + (size_t)b0 * IN + (c - 4) * 64;
            #pragma unroll
            for (int j = 0; j < 16; ++j) {
                int v = tid + j * 256; int r = v >> 5, q = v & 31;
                const float* s = src + (size_t)r * IN + 2 * q;
                uint32_t ph = pack_h2(s[0], s[1]);
                buf[r * 36 + q] = ph;
                g_xh[(size_t)(b0 + r) * (IN / 2) + (c - 4) * 32 + q] = ph;
            }
        } else {
            const float* src = d + (size_t)b0 * DEMO;
            #pragma unroll
            for (int j = 0; j < 4; ++j) {
                int v = tid + j * 256; int r = v >> 3, q = v & 7;
                const float* s = src + (size_t)r * DEMO + 2 * q;
                buf[r * 36 + q] = pack_h2(s[0], s[1]);
            }
        }
        __syncthreads();

        const int nks = (c == 12) ? 1 : 4;
        const int r = warp * 16 + g;
        for (int ks = 0; ks < nks; ++ks) {
            const int pb = ks * 8;
            uint32_t a[4];
            a[0] = buf[r * 36 + pb + t];
            a[1] = buf[(r + 8) * 36 + pb + t];
            a[2] = buf[r * 36 + pb + t + 4];
            a[3] = buf[(r + 8) * 36 + pb + t + 4];
            const int kp = c * 32 + pb;
            #pragma unroll
            for (int nf = 0; nf < 2; ++nf) {
                int n = nf * 8 + g;
                uint32_t bb0 = gsm[n * GWS_STRIDE + kp + t];
                uint32_t bb1 = gsm[n * GWS_STRIDE + kp + t + 4];
                mma_f16(acc[nf], a, bb0, bb1);
            }
        }
        __syncthreads();
    }

    float gb00 = gb[2 * t],     gb01 = gb[2 * t + 1];
    float gb10 = gb[8 + 2 * t], gb11 = gb[9 + 2 * t];
    const int rbase = b0 + warp * 16;
    #pragma unroll
    for (int half = 0; half < 2; ++half) {
        float v0 = acc[0][half * 2 + 0] + gb00;
        float v1 = acc[0][half * 2 + 1] + gb01;
        float v2 = acc[1][half * 2 + 0] + gb10;
        float v3 = acc[1][half * 2 + 1] + gb11;
        float m = fmaxf(fmaxf(v0, v1), fmaxf(v2, v3));
        m = fmaxf(m, __shfl_xor_sync(0xffffffffu, m, 1));
        m = fmaxf(m, __shfl_xor_sync(0xffffffffu, m, 2));
        float p0 = expf(v0 - m), p1 = expf(v1 - m);
        float p2 = expf(v2 - m), p3 = expf(v3 - m);
        float s = p0 + p1 + p2 + p3;
        s += __shfl_xor_sync(0xffffffffu, s, 1);
        s += __shfl_xor_sync(0xffffffffu, s, 2);
        float inv = 1.f / s;
        int row = rbase + g + half * 8;
        g_wgt[(size_t)row * NE + 2 * t]     = p0 * inv;
        g_wgt[(size_t)row * NE + 2 * t + 1] = p1 * inv;
        g_wgt[(size_t)row * NE + 8 + 2 * t] = p2 * inv;
        g_wgt[(size_t)row * NE + 9 + 2 * t] = p3 * inv;
    }
}

// ---------------- moe_main: R10/R13 frozen schedule + ldmatrix fragments ----------------
// SMEM u32 layout (52736 u32 = 210944 B):
//   [0, 41472)       A staging: XA 3 x (128*36)=13824 at 0 ; WA 3 x (256*36)=27648 at 13824
//     Hs (128 x 132) aliases [0, 16896)  (live: epilogue A -> end of phase B)
//   [41472, 50688)   W2 staging: 2 x (128*36)
//   [50688, 52736)   wts (float) 128 x 16
#define XA_OFF  0
#define XA_BUF  4608
#define WA_OFF  13824
#define WA_BUF  9216
#define HS_STRIDE 132
#define W2_OFF  41472
#define W2_BUF  4608
#define WTS_OFF 50688
#define SMEM_BYTES (52736 * 4)

__device__ __forceinline__ void stageA(uint32_t* sm, int tid, int b0, int e, int ci, int buf) {
    uint32_t* xs = sm + XA_OFF + buf * XA_BUF;
    uint32_t* ws = sm + WA_OFF + buf * WA_BUF;
    const uint32_t* xsrc = g_xh + (size_t)b0 * (IN / 2) + ci * 32;
    const uint32_t* wsrc = g_w1h + (size_t)e * HID * (IN / 2) + ci * 32;
    #pragma unroll
    for (int j = 0; j < 4; ++j) {
        int v = tid + j * 256;
        int r = v >> 3, q = (v & 7) * 4;
        cp16(xs + r * 36 + q, xsrc + (size_t)r * (IN / 2) + q);
    }
    #pragma unroll
    for (int j = 0; j < 8; ++j) {
        int v = tid + j * 256;
        int n = v >> 3, q = (v & 7) * 4;
        cp16(ws + n * 36 + q, wsrc + (size_t)n * (IN / 2) + q);
    }
}
__device__ __forceinline__ void stageB(uint32_t* sm, int tid, int e, int ci, int buf) {
    uint32_t* w2 = sm + W2_OFF + buf * W2_BUF;
    const uint32_t* src = g_w2h + (size_t)e * OUT * (HID / 2) + ci * 32;
    #pragma unroll
    for (int j = 0; j < 4; ++j) {
        int v = tid + j * 256;
        int o = v >> 3, q = (v & 7) * 4;
        cp16(w2 + o * 36 + q, src + (size_t)o * (HID / 2) + q);
    }
}

__global__ __launch_bounds__(256, 1) void moe_main(
    const float* __restrict__ b1, const float* __restrict__ b2,
    float* __restrict__ out) {
    extern __shared__ uint32_t smu[];
    const int tid  = threadIdx.x;
    const int warp = tid >> 5, lane = tid & 31;
    const int g = lane >> 2, t = lane & 3;
    const int b0 = blockIdx.x * 128;
    const uint32_t smb = smem_u32p(smu);       // shared byte base

    // per-lane ldmatrix row offsets (u32 units)
    const int l15 = lane & 15;
    const uint32_t ro_a = l15 * 36 + ((lane >> 4) << 2);                    // A tiles, stride 36
    const uint32_t ro_b = ((lane & 7) + ((lane >> 4) << 3)) * 36 + ((lane & 8) ? 4 : 0); // B tiles, stride 36
    const uint32_t ro_h = l15 * HS_STRIDE + ((lane >> 4) << 2);             // Hs, stride 132

    float* wts = (float*)(smu + WTS_OFF);
    for (int i = tid; i < 128 * NE; i += 256) wts[i] = g_wgt[(size_t)b0 * NE + i];

    const int wm  = (warp & 1) * 64;
    const int wn1 = (warp >> 1) * 64;
    const int wn2 = (warp >> 1) * 32;

    float acc2[4][4][4];
    #pragma unroll
    for (int a = 0; a < 4; ++a)
        #pragma unroll
        for (int b = 0; b < 4; ++b)
            #pragma unroll
            for (int c = 0; c < 4; ++c) acc2[a][b][c] = 0.f;

    __syncthreads();

    for (int e = 0; e < NE; ++e) {
        // ===== Phase A: H = relu(X @ W1_e^T + b1) * w  (K=512, 8 chunks of 64) =====
        float acc1[4][8][4];
        #pragma unroll
        for (int a = 0; a < 4; ++a)
            #pragma unroll
            for (int b = 0; b < 8; ++b)
                #pragma unroll
                for (int c = 0; c < 4; ++c) acc1[a][b][c] = 0.f;

        stageA(smu, tid, b0, e, 0, 0); cp_commit();
        stageA(smu, tid, b0, e, 1, 1); cp_commit();

        for (int ci = 0; ci < 8; ++ci) {
            if (ci < 7) cp_wait1(); else cp_wait0();
            __syncthreads();
            if (ci < 6) { stageA(smu, tid, b0, e, ci + 2, (ci + 2) % 3); cp_commit(); }
            const uint32_t xba = smb + (XA_OFF + (ci % 3) * XA_BUF) * 4;
            const uint32_t wba = smb + (WA_OFF + (ci % 3) * WA_BUF) * 4;
            #pragma unroll
            for (int ks = 0; ks < 4; ++ks) {
                const int pb = ks * 8;
                uint32_t a[4][4];
                #pragma unroll
                for (int mf = 0; mf < 4; ++mf)
                    ldsm_x4(a[mf], xba + ((wm + mf * 16) * 36 + pb + ro_a) * 4);
                #pragma unroll
                for (int nfp = 0; nfp < 4; ++nfp) {
                    uint32_t bb[4];
                    ldsm_x4(bb, wba + ((wn1 + nfp * 16) * 36 + pb + ro_b) * 4);
                    #pragma unroll
                    for (int mf = 0; mf < 4; ++mf) {
                        mma_f16(acc1[mf][2 * nfp],     a[mf], bb[0], bb[1]);
                        mma_f16(acc1[mf][2 * nfp + 1], a[mf], bb[2], bb[3]);
                    }
                }
            }
        }

        stageB(smu, tid, e, 0, 0); cp_commit();
        __syncthreads();

        // epilogue A: relu + bias + gate-weight scale, fp16 pack, store H
        #pragma unroll
        for (int mf = 0; mf < 4; ++mf) {
            int r0 = wm + mf * 16 + g, r1 = r0 + 8;
            float w0 = wts[r0 * NE + e], w1 = wts[r1 * NE + e];
            #pragma unroll
            for (int nf = 0; nf < 8; ++nf) {
                int c0 = wn1 + nf * 8 + 2 * t;
                int p  = c0 >> 1;
                float bb0 = b1[e * HID + c0], bb1 = b1[e * HID + c0 + 1];
                float v00 = fmaxf(acc1[mf][nf][0] + bb0, 0.f) * w0;
                float v01 = fmaxf(acc1[mf][nf][1] + bb1, 0.f) * w0;
                float v10 = fmaxf(acc1[mf][nf][2] + bb0, 0.f) * w1;
                float v11 = fmaxf(acc1[mf][nf][3] + bb1, 0.f) * w1;
                smu[r0 * HS_STRIDE + p] = pack_h2(v00, v01);
                smu[r1 * HS_STRIDE + p] = pack_h2(v10, v11);
            }
        }

        // ===== Phase B: out += (w*H_e) @ W2_e^T  (K=256, 4 chunks of 64) =====
        for (int ci = 0; ci < 4; ++ci) {
            int cur = ci & 1;
            cp_wait0(); __syncthreads();
            if (ci < 3) { stageB(smu, tid, e, ci + 1, cur ^ 1); cp_commit(); }
            const uint32_t w2ba = smb + (W2_OFF + cur * W2_BUF) * 4;
            #pragma unroll
            for (int ks = 0; ks < 4; ++ks) {
                const int pb  = ci * 32 + ks * 8;
                const int pb2 = ks * 8;
                uint32_t a[4][4];
                #pragma unroll
                for (int mf = 0; mf < 4; ++mf)
                    ldsm_x4(a[mf], smb + ((wm + mf * 16) * HS_STRIDE + pb + ro_h) * 4);
                #pragma unroll
                for (int nfp = 0; nfp < 2; ++nfp) {
                    uint32_t bb[4];
                    ldsm_x4(bb, w2ba + ((wn2 + nfp * 16) * 36 + pb2 + ro_b) * 4);
                    #pragma unroll
                    for (int mf = 0; mf < 4; ++mf) {
                        mma_f16(acc2[mf][2 * nfp],     a[mf], bb[0], bb[1]);
                        mma_f16(acc2[mf][2 * nfp + 1], a[mf], bb[2], bb[3]);
                    }
                }
            }
            __syncthreads();
        }
    }

    // ===== epilogue: out = acc2 + sum_e w[b,e] * b2[e,:] =====
    #pragma unroll
    for (int mf = 0; mf < 4; ++mf) {
        int r0 = wm + mf * 16 + g, r1 = r0 + 8;
        #pragma unroll
        for (int nf = 0; nf < 4; ++nf) {
            int c0 = wn2 + nf * 8 + 2 * t;
            float s0 = acc2[mf][nf][0], s1 = acc2[mf][nf][1];
            float s2 = acc2[mf][nf][2], s3 = acc2[mf][nf][3];
            #pragma unroll
            for (int e = 0; e < NE; ++e) {
                float bb0 = b2[e * OUT + c0], bb1 = b2[e * OUT + c0 + 1];
                float we0 = wts[r0 * NE + e], we1 = wts[r1 * NE + e];
                s0 += we0 * bb0; s1 += we0 * bb1;
                s2 += we1 * bb0; s3 += we1 * bb1;
            }
            out[(size_t)(b0 + r0) * OUT + c0]     = s0;
            out[(size_t)(b0 + r0) * OUT + c0 + 1] = s1;
            out[(size_t)(b0 + r1) * OUT + c0]     = s2;
            out[(size_t)(b0 + r1) * OUT + c0 + 1] = s3;
        }
    }
}

// ---------------- launch (2 kernels) ----------------
extern "C" void kernel_launch(void* const* d_in, const int* in_sizes, int n_in,
                              void* d_out, int out_size) {
    const float* x  = (const float*)d_in[0];
    const float* u  = (const float*)d_in[1];
    const float* dd = (const float*)d_in[2];
    const float* gW = (const float*)d_in[3];
    const float* gb = (const float*)d_in[4];
    const float* W1 = (const float*)d_in[5];
    const float* b1 = (const float*)d_in[6];
    const float* W2 = (const float*)d_in[7];
    const float* b2 = (const float*)d_in[8];
    float* out = (float*)d_out;

    cudaFuncSetAttribute(gate2_k, cudaFuncAttributeMaxDynamicSharedMemorySize,
                         GATE2_SMEM);
    cudaFuncSetAttribute(moe_main, cudaFuncAttributeMaxDynamicSharedMemorySize,
                         SMEM_BYTES);

    gate2_k<<<BB / 128, 256, GATE2_SMEM>>>(u, x, dd, gW, gb, W1, W2);
    moe_main<<<BB / 128, 256, SMEM_BYTES>>>(b1, b2, out);
}